// round 17
// baseline (speedup 1.0000x reference)
#include <cuda_runtime.h>
#include <cuda_fp16.h>
#include <cstdint>
#include <math.h>
#include <float.h>

#define BATCH 8
#define HIDC  256
#define ZCH   64
#define KCODE 512

// ---------------- scratch (device globals; no allocation allowed) ----------------
__device__ float g_h2a[BATCH * HIDC * 32 * 32];  // c2 out (residual source)
__device__ float g_h2b[BATCH * HIDC * 32 * 32];  // r0 out (residual source)

// packed split activations: per element u32 = {h:lo16 | l:hi16}  (ping-pong)
__device__ uint32_t g_sp1[BATCH * HIDC * 64 * 64];  // 33 MB
__device__ uint32_t g_sp2[BATCH * HIDC * 64 * 64];  // 33 MB

// fp16 split weights: per 32-k chunk: [h32 | ls32]
__device__ __half g_wc1 [HIDC * 2 * 64];
__device__ __half g_wc2 [HIDC * 2 * 4096];
__device__ __half g_wr03[HIDC * 2 * 2304];
__device__ __half g_wr01[HIDC * 2 * 256];
__device__ __half g_wr13[HIDC * 2 * 2304];
__device__ __half g_wr11[HIDC * 2 * 256];
__device__ __half g_wtz [ZCH  * 2 * 256];
__device__ __half g_wfz [HIDC * 2 * 64];
__device__ __half g_wt1e[4 * HIDC * 2 * 1024];
__device__ __half g_wt2e[4 * 64 * 2 * 1024];     // t2 subpixel, oc padded 3->64
__device__ float  g_t2bp[64];                    // t2 bias padded

// ================= helpers =================
__device__ __forceinline__ uint32_t smem_u32(const void* p) {
    uint32_t a;
    asm("{ .reg .u64 t; cvta.to.shared.u64 t, %1; cvt.u32.u64 %0, t; }" : "=r"(a) : "l"(p));
    return a;
}
#define SWZ128(o) ((o) ^ (((o) >> 3) & 0x70))
__device__ __forceinline__ void sts128(uint32_t a, uint4 v) {
    asm volatile("st.shared.v4.b32 [%0], {%1,%2,%3,%4};"
                 :: "r"(a), "r"(v.x), "r"(v.y), "r"(v.z), "r"(v.w) : "memory");
}
__device__ __forceinline__ void cpasync16(uint32_t saddr, const void* gaddr) {
    asm volatile("cp.async.cg.shared.global [%0], [%1], 16;"
                 :: "r"(saddr), "l"(gaddr) : "memory");
}
__device__ __forceinline__ void cpcommit() {
    asm volatile("cp.async.commit_group;" ::: "memory");
}
__device__ __forceinline__ void cpwait0() {
    asm volatile("cp.async.wait_group 0;" ::: "memory");
}
__device__ __forceinline__ void ldsm4(uint32_t* r, uint32_t addr) {
    asm volatile("ldmatrix.sync.aligned.m8n8.x4.shared.b16 {%0,%1,%2,%3}, [%4];"
                 : "=r"(r[0]), "=r"(r[1]), "=r"(r[2]), "=r"(r[3]) : "r"(addr));
}
__device__ __forceinline__ void mma16816(float* c, const uint32_t* a, const uint32_t* b) {
    asm volatile(
        "mma.sync.aligned.m16n8k16.row.col.f32.f16.f16.f32 "
        "{%0,%1,%2,%3}, {%4,%5,%6,%7}, {%8,%9}, {%0,%1,%2,%3};"
        : "+f"(c[0]), "+f"(c[1]), "+f"(c[2]), "+f"(c[3])
        : "r"(a[0]), "r"(a[1]), "r"(a[2]), "r"(a[3]), "r"(b[0]), "r"(b[1]));
}
__device__ __forceinline__ uint32_t prmt(uint32_t a, uint32_t b, uint32_t sel) {
    uint32_t r;
    asm("prmt.b32 %0, %1, %2, %3;" : "=r"(r) : "r"(a), "r"(b), "r"(sel));
    return r;
}
__device__ __forceinline__ uint32_t packsplit(float v) {
    __half h = __float2half_rn(v);
    __half l = __float2half_rn((v - __half2float(h)) * 2048.0f);
    return (uint32_t)__half_as_ushort(h) | ((uint32_t)__half_as_ushort(l) << 16);
}

// ======= weight split: fp32 -> per-32k-chunk [h32|ls32] fp16 rows =======
__global__ void wsplit16(const float* __restrict__ W, __half* __restrict__ E,
                         int Cout, int K)
{
    int i = blockIdx.x * blockDim.x + threadIdx.x;
    if (i >= Cout * K) return;
    int oc = i / K, k = i - oc * K;
    int c = k >> 5, j = k & 31;
    float v = W[i];
    __half h = __float2half_rn(v);
    __half ls = __float2half_rn((v - __half2float(h)) * 2048.0f);
    long base = (long)oc * 2 * K + (long)c * 64;
    E[base + j]      = h;
    E[base + 32 + j] = ls;
}

// c1 weights: source K=48 (3ch x 16 taps), emitted K=64 with zero pad (ch 3)
__global__ void wsplit_c1(const float* __restrict__ W, __half* __restrict__ E)
{
    int i = blockIdx.x * blockDim.x + threadIdx.x;
    if (i >= 256 * 64) return;
    int oc = i >> 6, k = i & 63;
    float v = (k < 48) ? W[oc * 48 + k] : 0.f;
    __half h = __float2half_rn(v);
    __half ls = __float2half_rn((v - __half2float(h)) * 2048.0f);
    int c = k >> 5, j = k & 31;
    long base = (long)oc * 128 + c * 64;
    E[base + j]      = h;
    E[base + 32 + j] = ls;
}

// t1 subpixel weights: direct from t1_w (256,256,4,4) -> [4][256][2*1024] split
__global__ void wt1_split(const float* __restrict__ w, __half* __restrict__ E)
{
    int i = blockIdx.x * blockDim.x + threadIdx.x;
    if (i >= 4 * 256 * 1024) return;
    int k  = i & 1023;
    int oc = (i >> 10) & 255;
    int pz = i >> 18;
    int ic = k >> 2, ky = (k >> 1) & 1, kx = k & 1;
    int p = pz >> 1, q = pz & 1;
    float v = w[((long)(ic * 256 + oc) << 4) + (3 - p - 2 * ky) * 4 + (3 - q - 2 * kx)];
    __half h = __float2half_rn(v);
    __half ls = __float2half_rn((v - __half2float(h)) * 2048.0f);
    int c = k >> 5, j = k & 31;
    long base = (long)(pz * 256 + oc) * 2048 + c * 64;
    E[base + j]      = h;
    E[base + 32 + j] = ls;
}

// t2 subpixel weights: t2_w (256,3,4,4) -> [4][64][2*1024] split, oc padded; + bias pad
__global__ void wt2_split(const float* __restrict__ w, const float* __restrict__ b,
                          __half* __restrict__ E, float* __restrict__ bp)
{
    int i = blockIdx.x * blockDim.x + threadIdx.x;
    if (i < 64) bp[i] = (i < 3) ? b[i] : 0.f;
    if (i >= 4 * 64 * 1024) return;
    int k  = i & 1023;
    int oc = (i >> 10) & 63;
    int pz = i >> 16;
    int ic = k >> 2, ky = (k >> 1) & 1, kx = k & 1;
    int p = pz >> 1, q = pz & 1;
    float v = 0.f;
    if (oc < 3)
        v = w[((long)(ic * 3 + oc) << 4) + (3 - p - 2 * ky) * 4 + (3 - q - 2 * kx)];
    __half h = __float2half_rn(v);
    __half ls = __float2half_rn((v - __half2float(h)) * 2048.0f);
    int c = k >> 5, j = k & 31;
    long base = (long)(pz * 64 + oc) * 2048 + c * 64;
    E[base + j]      = h;
    E[base + 32 + j] = ls;
}

// x split with channel pad 3->4: out [8][4][16384] packed
__global__ void asplit_pad(const float* __restrict__ x, uint32_t* __restrict__ outp)
{
    int i = blockIdx.x * blockDim.x + threadIdx.x;
    if (i >= 8 * 4 * 4096) return;
    int hw4 = i & 4095;
    int r = i >> 12;
    int c = r & 3;
    int b = r >> 2;
    uint4 o = make_uint4(0, 0, 0, 0);
    if (c < 3) {
        float4 v = reinterpret_cast<const float4*>(x + ((long)(b * 3 + c) << 14))[hw4];
        o.x = packsplit(v.x); o.y = packsplit(v.y);
        o.z = packsplit(v.z); o.w = packsplit(v.w);
    }
    reinterpret_cast<uint4*>(outp)[((long)r << 12) + hw4] = o;
}

// =======================================================================
// mma.sync implicit-GEMM conv (fp16 2-way split w/ rescale, 3 terms).
//   CTA: 64 oc x 64 px. BK=32. 8 warps as 4(m) x 2(n); warp tile 16x32.
// Round-17: SUBPIX epilogue supports split-store (spout) and act==2
// (sigmoid + store only oc<3, for t2). Mrows = weight rows per parity
// (decoupled from Cout addressing for the padded-t2 case).
// =======================================================================
template<int KH, int KW, bool SUBPIX>
__global__ __launch_bounds__(256, 2) void conv_mma(
    const __half* __restrict__ Wc,
    const uint32_t* __restrict__ inp,
    const float* __restrict__ bias, const float* __restrict__ res,
    float* __restrict__ out, uint32_t* __restrict__ spout,
    int storef, int srelu,
    int Cin, int Hin, int Win, int Cout, int Hout, int Wout,
    int stride, int pad, int K, int act,
    int Hfull, int Wfull, int Mrows)
{
    constexpr int KHW = KH * KW;
    constexpr bool REGP = (32 % KHW) == 0;
    __shared__ __align__(16) char sAm[2][64 * 128];
    __shared__ __align__(16) char sBm[2][64 * 128];

    const int tid  = threadIdx.x;
    const int wid  = tid >> 5;
    const int lane = tid & 31;
    const int m0 = blockIdx.y * 64;
    const int n0 = blockIdx.x * 64;
    const int HW = Hout * Wout;

    uint32_t sAb[2], sBb[2];
    sAb[0] = smem_u32(sAm[0]); sAb[1] = smem_u32(sAm[1]);
    sBb[0] = smem_u32(sBm[0]); sBb[1] = smem_u32(sBm[1]);

    int par_y = 0, par_x = 0;
    const __half* Wb = Wc;
    if (SUBPIX) {
        int pz = blockIdx.z;
        par_y = pz >> 1; par_x = pz & 1;
        Wb += (long)pz * Mrows * 2 * K;
    }

    const int px  = tid & 63;
    const int seg = tid >> 6;
    const int n   = n0 + px;
    const int bimg = n / HW;
    const int hw   = n - bimg * HW;
    const int oy   = hw / Wout, ox = hw - oy * Wout;
    const uint32_t* inb = inp + (long)bimg * Cin * Hin * Win;
    int iy0, ix0;
    if (SUBPIX) { iy0 = oy - (1 - par_y); ix0 = ox - (1 - par_x); }
    else        { iy0 = oy * stride - pad; ix0 = ox * stride - pad; }

    int pbase[8];
    unsigned vmask = 0;
    if (REGP) {
        #pragma unroll
        for (int e = 0; e < 8; e++) {
            int kk = seg * 8 + e;
            int ic0 = kk / KHW;
            int rr = kk - ic0 * KHW;
            int ky = rr / KW, kx = rr - ky * KW;
            int iy = iy0 + ky, ix = ix0 + kx;
            pbase[e] = ic0 * Hin * Win + iy * Win + ix;
            if ((unsigned)iy < (unsigned)Hin && (unsigned)ix < (unsigned)Win)
                vmask |= (1u << e);
        }
    }
    const int dic = REGP ? (32 / KHW) * Hin * Win : 0;

    const int wm = (wid & 3) * 16;
    const int wn = (wid >> 2) * 32;

    float acc[4][4];
    float accl[4][4];
    #pragma unroll
    for (int nt = 0; nt < 4; nt++)
        #pragma unroll
        for (int e = 0; e < 4; e++) { acc[nt][e] = 0.f; accl[nt][e] = 0.f; }

    const long K2 = 2 * (long)K;
    const int nc_iters = K / 32;

    const int arow = tid >> 3;
    const int ac16 = tid & 7;
    const __half* Arow0 = Wb + (long)(m0 + arow) * K2 + ac16 * 8;
    const __half* Arow1 = Wb + (long)(m0 + arow + 32) * K2 + ac16 * 8;
    const uint32_t sA0off = SWZ128(arow * 128 + ac16 * 16);
    const uint32_t sA1off = SWZ128((arow + 32) * 128 + ac16 * 16);

    uint32_t raw[8];

    auto issueA = [&](int cb, int buf) {
        const long kb = (long)cb * 64;
        cpasync16(sAb[buf] + sA0off, Arow0 + kb);
        cpasync16(sAb[buf] + sA1off, Arow1 + kb);
    };
    auto loadB = [&](int cb) {
        if (REGP) {
            const int off = cb * dic;
            #pragma unroll
            for (int e = 0; e < 8; e++)
                raw[e] = ((vmask >> e) & 1) ? inb[off + pbase[e]] : 0u;
        } else {
            const int kb = cb * 32 + seg * 8;
            #pragma unroll
            for (int e = 0; e < 8; e++) {
                int k = kb + e;
                int ic = k / KHW;
                int r2 = k - ic * KHW;
                int ky = r2 / KW, kx = r2 - ky * KW;
                int iy = iy0 + ky, ix = ix0 + kx;
                uint32_t pv = 0;
                if ((unsigned)iy < (unsigned)Hin && (unsigned)ix < (unsigned)Win)
                    pv = inb[(ic * Hin + iy) * Win + ix];
                raw[e] = pv;
            }
        }
    };
    auto storeB = [&](int buf) {
        uint32_t hp[4], lp[4];
        #pragma unroll
        for (int q = 0; q < 4; q++) {
            hp[q] = prmt(raw[2 * q], raw[2 * q + 1], 0x5410);
            lp[q] = prmt(raw[2 * q], raw[2 * q + 1], 0x7632);
        }
        sts128(sBb[buf] + SWZ128(px * 128 + seg * 16),      make_uint4(hp[0], hp[1], hp[2], hp[3]));
        sts128(sBb[buf] + SWZ128(px * 128 + 64 + seg * 16), make_uint4(lp[0], lp[1], lp[2], lp[3]));
    };

    issueA(0, 0);
    cpcommit();
    loadB(0);
    cpwait0();
    storeB(0);
    __syncthreads();

    int cur = 0;
    for (int cb = 0; cb < nc_iters; cb++) {
        if (cb + 1 < nc_iters) {
            issueA(cb + 1, cur ^ 1);
            cpcommit();
            loadB(cb + 1);
        }
        const uint32_t sA = sAb[cur];
        const uint32_t sB = sBb[cur];
        #pragma unroll
        for (int s = 0; s < 2; s++) {
            uint32_t Ah[4], Al[4];
            {
                int row = wm + (lane & 15);
                int kby = s * 32 + ((lane >> 4) << 4);
                ldsm4(Ah, sA + SWZ128(row * 128 + kby));
                ldsm4(Al, sA + SWZ128(row * 128 + 64 + kby));
            }
            uint32_t Bh[2][4], Bl[2][4];
            #pragma unroll
            for (int ntp = 0; ntp < 2; ntp++) {
                int nrow = wn + ntp * 16 + ((lane >> 4) << 3) + (lane & 7);
                int kby  = s * 32 + (((lane >> 3) & 1) << 4);
                ldsm4(Bh[ntp], sB + SWZ128(nrow * 128 + kby));
                ldsm4(Bl[ntp], sB + SWZ128(nrow * 128 + 64 + kby));
            }
            #pragma unroll
            for (int nt = 0; nt < 4; nt++) {
                const uint32_t* bh = &Bh[nt >> 1][(nt & 1) * 2];
                const uint32_t* bl = &Bl[nt >> 1][(nt & 1) * 2];
                mma16816(acc[nt],  Ah, bh);
                mma16816(accl[nt], Ah, bl);
                mma16816(accl[nt], Al, bh);
            }
        }
        if (cb + 1 < nc_iters) {
            cpwait0();
            storeB(cur ^ 1);
            __syncthreads();
            cur ^= 1;
        }
    }

    // ---- epilogue ----
    const float INV = 1.0f / 2048.0f;
    const long HWf = (long)Hfull * Wfull;
    const int bimg0 = n0 / HW;
    const int hw0 = n0 - bimg0 * HW;
    const long obase = (long)bimg0 * Cout * HWf;

    #pragma unroll
    for (int nt = 0; nt < 4; nt++) {
        float c0 = acc[nt][0] + accl[nt][0] * INV;
        float c1 = acc[nt][1] + accl[nt][1] * INV;
        float c2 = acc[nt][2] + accl[nt][2] * INV;
        float c3 = acc[nt][3] + accl[nt][3] * INV;
        int oc0 = m0 + wm + (lane >> 2);
        int oc1 = oc0 + 8;
        int ncol = hw0 + wn + nt * 8 + (lane & 3) * 2;
        float b0 = bias[oc0], b1 = bias[oc1];
        c0 += b0; c1 += b0; c2 += b1; c3 += b1;
        if (!SUBPIX) {
            long i0 = obase + (long)oc0 * HWf + ncol;
            long i1 = obase + (long)oc1 * HWf + ncol;
            if (res) {
                float2 r0 = *reinterpret_cast<const float2*>(res + i0);
                float2 r1 = *reinterpret_cast<const float2*>(res + i1);
                c0 += r0.x; c1 += r0.y; c2 += r1.x; c3 += r1.y;
            }
            float f0 = c0, f1 = c1, f2 = c2, f3 = c3;
            if (act == 1) {
                f0 = fmaxf(c0, 0.f); f1 = fmaxf(c1, 0.f);
                f2 = fmaxf(c2, 0.f); f3 = fmaxf(c3, 0.f);
            }
            if (storef) {
                *reinterpret_cast<float2*>(out + i0) = make_float2(f0, f1);
                *reinterpret_cast<float2*>(out + i1) = make_float2(f2, f3);
            }
            if (spout) {
                float s0 = f0, s1 = f1, s2 = f2, s3 = f3;
                if (act == 0 && srelu) {
                    s0 = fmaxf(c0, 0.f); s1 = fmaxf(c1, 0.f);
                    s2 = fmaxf(c2, 0.f); s3 = fmaxf(c3, 0.f);
                }
                uint2 p0 = make_uint2(packsplit(s0), packsplit(s1));
                uint2 p1 = make_uint2(packsplit(s2), packsplit(s3));
                *reinterpret_cast<uint2*>(spout + i0) = p0;
                *reinterpret_cast<uint2*>(spout + i1) = p1;
            }
        } else {
            if (act == 1) {
                c0 = fmaxf(c0, 0.f); c1 = fmaxf(c1, 0.f);
                c2 = fmaxf(c2, 0.f); c3 = fmaxf(c3, 0.f);
            } else if (act == 2) {
                c0 = 1.f / (1.f + expf(-c0));
                c1 = 1.f / (1.f + expf(-c1));
                c2 = 1.f / (1.f + expf(-c2));
                c3 = 1.f / (1.f + expf(-c3));
            }
            const bool w0 = (act != 2) || (oc0 < 3);
            const bool w1 = (act != 2) || (oc1 < 3);
            int eoy0 = ncol / Wout, eox0 = ncol - eoy0 * Wout;
            int nc1 = ncol + 1;
            int eoy1 = nc1 / Wout, eox1 = nc1 - eoy1 * Wout;
            long fy0 = 2 * eoy0 + par_y, fx0 = 2 * eox0 + par_x;
            long fy1 = 2 * eoy1 + par_y, fx1 = 2 * eox1 + par_x;
            long a00 = obase + (long)oc0 * HWf + fy0 * Wfull + fx0;
            long a01 = obase + (long)oc0 * HWf + fy1 * Wfull + fx1;
            long a10 = obase + (long)oc1 * HWf + fy0 * Wfull + fx0;
            long a11 = obase + (long)oc1 * HWf + fy1 * Wfull + fx1;
            if (storef) {
                if (w0) { out[a00] = c0; out[a01] = c1; }
                if (w1) { out[a10] = c2; out[a11] = c3; }
            }
            if (spout) {
                if (w0) { spout[a00] = packsplit(c0); spout[a01] = packsplit(c1); }
                if (w1) { spout[a10] = packsplit(c2); spout[a11] = packsplit(c3); }
            }
        }
    }
}

// ---------------- VQ: one warp per z-vector; emits ids, e_k fp32 + split ----------------
__global__ __launch_bounds__(128) void vq_kernel(
    const float* __restrict__ z, const float* __restrict__ cb,
    float* __restrict__ ek, float* __restrict__ ids_out,
    uint32_t* __restrict__ eksp)
{
    const int warp = threadIdx.x >> 5;
    const int lane = threadIdx.x & 31;
    const int n = blockIdx.x * 4 + warp;
    const int b  = n >> 10;
    const int hw = n & 1023;

    __shared__ float zs[4][ZCH];
    const float* zb = z + (long)b * ZCH * 1024 + hw;
    zs[warp][lane]      = zb[(long)lane * 1024];
    zs[warp][lane + 32] = zb[(long)(lane + 32) * 1024];
    __syncwarp();

    float best = FLT_MAX;
    int bi = 0;
    for (int k = lane; k < KCODE; k += 32) {
        const float* c = cb + k * ZCH;
        float s = 0.f;
        #pragma unroll 16
        for (int ci = 0; ci < ZCH; ci++) {
            float cv = c[ci];
            s = fmaf(cv, cv - 2.f * zs[warp][ci], s);
        }
        if (s < best) { best = s; bi = k; }
    }
    #pragma unroll
    for (int off = 16; off; off >>= 1) {
        float ov = __shfl_down_sync(0xffffffffu, best, off);
        int   oi = __shfl_down_sync(0xffffffffu, bi,   off);
        if (ov < best || (ov == best && oi < bi)) { best = ov; bi = oi; }
    }
    bi = __shfl_sync(0xffffffffu, bi, 0);

    if (lane == 0) ids_out[n] = (float)bi;
    const float* c = cb + bi * ZCH;
    float* ekb = ek + (long)b * ZCH * 1024 + hw;
    uint32_t* spb = eksp + (long)b * ZCH * 1024 + hw;
    float v0 = c[lane], v1 = c[lane + 32];
    ekb[(long)lane * 1024]        = v0;
    ekb[(long)(lane + 32) * 1024] = v1;
    spb[(long)lane * 1024]        = packsplit(v0);
    spb[(long)(lane + 32) * 1024] = packsplit(v1);
}

// ---------------- host ----------------
extern "C" void kernel_launch(void* const* d_in, const int* in_sizes, int n_in,
                              void* d_out, int out_size)
{
    const float* x      = (const float*)d_in[0];
    const float* c1_w   = (const float*)d_in[1];
    const float* c1_b   = (const float*)d_in[2];
    const float* c2_w   = (const float*)d_in[3];
    const float* c2_b   = (const float*)d_in[4];
    const float* r0_w3  = (const float*)d_in[5];
    const float* r0_b3  = (const float*)d_in[6];
    const float* r0_w1  = (const float*)d_in[7];
    const float* r0_b1  = (const float*)d_in[8];
    const float* r1_w3  = (const float*)d_in[9];
    const float* r1_b3  = (const float*)d_in[10];
    const float* r1_w1  = (const float*)d_in[11];
    const float* r1_b1  = (const float*)d_in[12];
    const float* to_z_w = (const float*)d_in[13];
    const float* to_z_b = (const float*)d_in[14];
    const float* codebk = (const float*)d_in[15];
    const float* fz_w   = (const float*)d_in[16];
    const float* fz_b   = (const float*)d_in[17];
    const float* t1_w   = (const float*)d_in[18];
    const float* t1_b   = (const float*)d_in[19];
    const float* t2_w   = (const float*)d_in[20];
    const float* t2_b   = (const float*)d_in[21];
    float* out = (float*)d_out;

    const long ZE_OFF  = 393216;
    const long EK_OFF  = 917504;
    const long IDS_OFF = 1441792;

    float *h2a, *h2b, *t2bp;
    uint32_t *sp1, *sp2;
    __half *wc1, *wc2, *wr03, *wr01, *wr13, *wr11, *wtz, *wfz, *wt1e, *wt2e;
    cudaGetSymbolAddress((void**)&h2a, g_h2a);
    cudaGetSymbolAddress((void**)&h2b, g_h2b);
    cudaGetSymbolAddress((void**)&t2bp, g_t2bp);
    cudaGetSymbolAddress((void**)&sp1, g_sp1);
    cudaGetSymbolAddress((void**)&sp2, g_sp2);
    cudaGetSymbolAddress((void**)&wc1,  g_wc1);
    cudaGetSymbolAddress((void**)&wc2,  g_wc2);
    cudaGetSymbolAddress((void**)&wr03, g_wr03);
    cudaGetSymbolAddress((void**)&wr01, g_wr01);
    cudaGetSymbolAddress((void**)&wr13, g_wr13);
    cudaGetSymbolAddress((void**)&wr11, g_wr11);
    cudaGetSymbolAddress((void**)&wtz,  g_wtz);
    cudaGetSymbolAddress((void**)&wfz,  g_wfz);
    cudaGetSymbolAddress((void**)&wt1e, g_wt1e);
    cudaGetSymbolAddress((void**)&wt2e, g_wt2e);

    // (1) c2 weight split
    wsplit16<<<(256 * 4096 + 255) / 256, 256>>>(c2_w, wc2, 256, 4096);
    // (2) x split (channel-padded) -> sp2
    asplit_pad<<<(8 * 4 * 4096 + 255) / 256, 256>>>(x, sp2);
    // (3) c1 weight split (K padded 48->64)
    wsplit_c1<<<(256 * 64 + 255) / 256, 256>>>(c1_w, wc1);
    // (4) c1: 4->256, k4 s2 p1, relu (mma); split-only -> sp1   <-- profiled
    conv_mma<4, 4, false><<<dim3(512, 4), 256>>>(
        wc1, sp2, c1_b, nullptr, nullptr, sp1, 0, 0,
        4, 128, 128, 256, 64, 64, 2, 1, 64, 1, 64, 64, 256);
    // (5) c2: f32 h2a + split sp2
    conv_mma<4, 4, false><<<dim3(128, 4), 256>>>(
        wc2, sp1, c2_b, nullptr, h2a, sp2, 1, 0,
        256, 64, 64, 256, 32, 32, 2, 1, 4096, 1, 32, 32, 256);

    // r0 3x3: split-only (relu'd) -> sp1
    wsplit16<<<(256 * 2304 + 255) / 256, 256>>>(r0_w3, wr03, 256, 2304);
    conv_mma<3, 3, false><<<dim3(128, 4), 256>>>(
        wr03, sp2, r0_b3, nullptr, nullptr, sp1, 0, 1,
        256, 32, 32, 256, 32, 32, 1, 1, 2304, 0, 32, 32, 256);
    // r0 1x1: res h2a; f32 h2b + split(relu) sp2
    wsplit16<<<(256 * 256 + 255) / 256, 256>>>(r0_w1, wr01, 256, 256);
    conv_mma<1, 1, false><<<dim3(128, 4), 256>>>(
        wr01, sp1, r0_b1, h2a, h2b, sp2, 1, 1,
        256, 32, 32, 256, 32, 32, 1, 0, 256, 0, 32, 32, 256);
    // r1 3x3: split-only (relu'd) -> sp1
    wsplit16<<<(256 * 2304 + 255) / 256, 256>>>(r1_w3, wr13, 256, 2304);
    conv_mma<3, 3, false><<<dim3(128, 4), 256>>>(
        wr13, sp2, r1_b3, nullptr, nullptr, sp1, 0, 1,
        256, 32, 32, 256, 32, 32, 1, 1, 2304, 0, 32, 32, 256);
    // r1 1x1: res h2b; split-only (no relu) -> sp2
    wsplit16<<<(256 * 256 + 255) / 256, 256>>>(r1_w1, wr11, 256, 256);
    conv_mma<1, 1, false><<<dim3(128, 4), 256>>>(
        wr11, sp1, r1_b1, h2b, nullptr, sp2, 0, 0,
        256, 32, 32, 256, 32, 32, 1, 0, 256, 0, 32, 32, 256);

    // to_z: 256->64 (mma), f32 -> z_e
    wsplit16<<<(64 * 256 + 255) / 256, 256>>>(to_z_w, wtz, 64, 256);
    conv_mma<1, 1, false><<<dim3(128, 1), 256>>>(
        wtz, sp2, to_z_b, nullptr, out + ZE_OFF, nullptr, 1, 0,
        256, 32, 32, 64, 32, 32, 1, 0, 256, 0, 32, 32, 64);

    // VQ: ids + e_k fp32 + e_k split -> sp1
    vq_kernel<<<2048, 128>>>(out + ZE_OFF, codebk, out + EK_OFF, out + IDS_OFF, sp1);

    // from_z: 64->256, relu (mma); split-only -> sp2
    wsplit16<<<(256 * 64 + 255) / 256, 256>>>(fz_w, wfz, 256, 64);
    conv_mma<1, 1, false><<<dim3(128, 4), 256>>>(
        wfz, sp1, fz_b, nullptr, nullptr, sp2, 0, 0,
        64, 32, 32, 256, 32, 32, 1, 0, 64, 1, 32, 32, 256);

    // t1: convT as 4 subpixel 2x2 convs (mma), relu; split-only -> sp1
    wt1_split<<<(4 * 256 * 1024 + 255) / 256, 256>>>(t1_w, wt1e);
    conv_mma<2, 2, true><<<dim3(128, 4, 4), 256>>>(
        wt1e, sp2, t1_b, nullptr, nullptr, sp1, 0, 0,
        256, 32, 32, 256, 32, 32, 1, 0, 1024, 1, 64, 64, 256);

    // t2: convT 256->3 as 4 subpixel 2x2 convs (mma, oc padded to 64), sigmoid
    wt2_split<<<(4 * 64 * 1024 + 255) / 256, 256>>>(t2_w, t2_b, wt2e, t2bp);
    conv_mma<2, 2, true><<<dim3(512, 1, 4), 256>>>(
        wt2e, sp1, t2bp, nullptr, out, nullptr, 1, 0,
        256, 64, 64, 3, 64, 64, 1, 0, 1024, 2, 128, 128, 64);
}